// round 1
// baseline (speedup 1.0000x reference)
#include <cuda_runtime.h>
#include <math.h>

#define BB   16
#define CH   64
#define HH   256
#define WW   256
#define MD   16
#define NIMG (BB*CH)   // 1024

// ---------------- scratch (static __device__ allocations only) ----------------
__device__ __align__(16) float g_X1 [NIMG*HH*32];     // 33.5 MB  [img][y][2kx+ri]
__device__ __align__(16) float g_CFT[NIMG*512*2];     // 4 MB     [img][m][ri], m=kyi*16+kx
__device__ __align__(16) float g_OFT[NIMG*512*2];     // 4 MB
__device__ __align__(16) float g_G  [NIMG*HH*WW];     // 268 MB   global-branch output
__device__ __align__(16) float g_tabA [256*32];       // forward x-DFT twiddles [x][n]
__device__ __align__(16) float g_tabFT[32*256];       // inverse x-synth (scaled) [n][x]
__device__ __align__(16) float g_cosT[256];
__device__ __align__(16) float g_sinT[256];
__device__ __align__(16) float g_wT [CH*9*CH];        // conv weights [ci][tap][co]

// ---------------- f32x2 helpers ----------------
__device__ __forceinline__ unsigned long long pack2(float v) {
    unsigned long long d;
    asm("mov.b64 %0, {%1, %2};" : "=l"(d) : "f"(v), "f"(v));
    return d;
}
__device__ __forceinline__ unsigned long long fma2(unsigned long long a,
                                                   unsigned long long b,
                                                   unsigned long long c) {
    unsigned long long d;
    asm("fma.rn.f32x2 %0, %1, %2, %3;" : "=l"(d) : "l"(a), "l"(b), "l"(c));
    return d;
}

// ---------------- init: twiddle tables + conv weight reorder ----------------
__global__ void k_init(const float* __restrict__ conv_w) {
    const float TWO_PI = 6.28318530717958647692f;
    int tid = blockIdx.x * blockDim.x + threadIdx.x;
    int stride = gridDim.x * blockDim.x;

    if (tid < 256) {
        float ang = TWO_PI * (float)tid / 256.0f;
        g_cosT[tid] = cosf(ang);
        g_sinT[tid] = sinf(ang);
    }
    // forward table: [x][n], n=2kx -> cos, n=2kx+1 -> -sin   (e^{-i t})
    for (int idx = tid; idx < 256*32; idx += stride) {
        int x = idx >> 5, n = idx & 31, kx = n >> 1;
        float ang = TWO_PI * (float)((kx * x) & 255) / 256.0f;
        g_tabA[idx] = (n & 1) ? -sinf(ang) : cosf(ang);
    }
    // inverse synth table: [n][x], scaled (DC x1, others x2, /65536)
    for (int idx = tid; idx < 32*256; idx += stride) {
        int n = idx >> 8, x = idx & 255, kx = n >> 1;
        float sc = (kx == 0 ? 1.0f : 2.0f) / 65536.0f;
        float ang = TWO_PI * (float)((kx * x) & 255) / 256.0f;
        g_tabFT[idx] = (n & 1) ? -sc * sinf(ang) : sc * cosf(ang);
    }
    // conv weights OIHW -> [ci][tap][co]
    for (int idx = tid; idx < CH*9*CH; idx += stride) {
        int co = idx & 63;
        int rest = idx >> 6;
        int t  = rest % 9;
        int ci = rest / 9;
        g_wT[idx] = conv_w[(co*CH + ci)*9 + t];
    }
}

// ---------------- Kernel A: partial x-DFT (kx 0..15), real -> complex ----------------
// 2048 blocks x 256 thr; block handles 128 rows (8 rows per pass, warp-per-row)
__global__ void __launch_bounds__(256) kA(const float* __restrict__ c) {
    __shared__ float tab[8192];
    __shared__ float rows[8][256];
    int tid = threadIdx.x;
    for (int i = tid; i < 8192; i += 256) tab[i] = g_tabA[i];
    __syncthreads();
    int w = tid >> 5, lane = tid & 31;
    int rowBase = blockIdx.x * 128;
    for (int it = 0; it < 16; it++) {
        int row = rowBase + it*8 + w;                 // global row = img*256 + y
        const float* src = c + (size_t)row * 256;
        #pragma unroll
        for (int k = 0; k < 8; k++) rows[w][lane + k*32] = src[lane + k*32];
        __syncwarp();
        float a0 = 0.f, a1 = 0.f, a2 = 0.f, a3 = 0.f;
        #pragma unroll 4
        for (int x = 0; x < 256; x += 4) {
            a0 += rows[w][x+0] * tab[(x+0)*32 + lane];
            a1 += rows[w][x+1] * tab[(x+1)*32 + lane];
            a2 += rows[w][x+2] * tab[(x+2)*32 + lane];
            a3 += rows[w][x+3] * tab[(x+3)*32 + lane];
        }
        g_X1[(size_t)row*32 + lane] = (a0 + a1) + (a2 + a3);
        __syncwarp();
    }
}

// ---------------- Kernel B: y-DFT to 32 ky modes ----------------
// 1024 blocks (one per image), 512 thr; thread = (kyi, kx)
__global__ void __launch_bounds__(512) kB() {
    __shared__ float xs[8192];
    __shared__ float csm[256], ssm[256];
    int tid = threadIdx.x;
    int img = blockIdx.x;
    const float* src = g_X1 + (size_t)img * 8192;
    for (int i = tid; i < 8192; i += 512) xs[i] = src[i];
    if (tid < 256) { csm[tid] = g_cosT[tid]; ssm[tid] = g_sinT[tid]; }
    __syncthreads();
    int kyi = tid >> 4, kx = tid & 15;
    int ky = (kyi < 16) ? kyi : kyi + 224;            // 240..255
    float ar = 0.f, ai = 0.f;
    for (int y = 0; y < 256; y++) {
        int j = (ky * y) & 255;
        float cv = csm[j], sv = ssm[j];
        float2 v = *(const float2*)&xs[y*32 + 2*kx];
        ar += v.x * cv + v.y * sv;                    // (xr+ixi)(c - i s)
        ai += v.y * cv - v.x * sv;
    }
    *(float2*)&g_CFT[((size_t)img*512 + tid)*2] = make_float2(ar, ai);
}

// ---------------- Kernel C: per-mode 64x64 complex channel mix ----------------
// 512 blocks (one per mode), 128 thr
__global__ void __launch_bounds__(128) kC(const float* __restrict__ w1r, const float* __restrict__ w1i,
                                          const float* __restrict__ w2r, const float* __restrict__ w2i) {
    __shared__ float wr_s[4096], wi_s[4096], cf_s[2048];
    int tid = threadIdx.x;
    int m = blockIdx.x;
    int kyi = m >> 4, kx = m & 15;
    const float* br; const float* bi; int woff;
    if (kyi < 16) { br = w1r; bi = w1i; woff = kyi*16 + kx; }
    else          { br = w2r; bi = w2i; woff = (kyi-16)*16 + kx; }
    for (int idx = tid; idx < 4096; idx += 128) {     // idx = i*64+o
        wr_s[idx] = br[idx*256 + woff];
        wi_s[idx] = bi[idx*256 + woff];
    }
    for (int idx = tid; idx < 1024; idx += 128) {     // idx = b*64+i
        float2 v = *(const float2*)&g_CFT[((size_t)idx*512 + m)*2];
        cf_s[2*idx] = v.x; cf_s[2*idx+1] = v.y;
    }
    __syncthreads();
    int o = tid & 63, h = tid >> 6;                   // h in {0,1}, 8 batches each
    float aR[8], aI[8];
    #pragma unroll
    for (int q = 0; q < 8; q++) { aR[q] = 0.f; aI[q] = 0.f; }
    for (int i = 0; i < 64; i++) {
        float wr = wr_s[i*64 + o], wi = wi_s[i*64 + o];
        #pragma unroll
        for (int q = 0; q < 8; q++) {
            int b = h*8 + q;
            float cr = cf_s[(b*64 + i)*2], ci2 = cf_s[(b*64 + i)*2 + 1];
            aR[q] += cr*wr - ci2*wi;
            aI[q] += cr*wi + ci2*wr;
        }
    }
    #pragma unroll
    for (int q = 0; q < 8; q++) {
        int b = h*8 + q;
        *(float2*)&g_OFT[(((size_t)b*64 + o)*512 + m)*2] = make_float2(aR[q], aI[q]);
    }
}

// ---------------- Kernel D: inverse transform -> G ----------------
// 1024 blocks (one per output image), 256 thr
__global__ void __launch_bounds__(256) kD() {
    __shared__ float tmp[256*33];                     // padded stride 33
    __shared__ float oft_s[1024];
    __shared__ float csm[256], ssm[256];
    int tid = threadIdx.x;
    int img = blockIdx.x;
    const float* src = g_OFT + (size_t)img * 1024;
    for (int i = tid; i < 1024; i += 256) oft_s[i] = src[i];
    if (tid < 256) { csm[tid] = g_cosT[tid]; ssm[tid] = g_sinT[tid]; }
    __syncthreads();
    {   // phase 2: y-iDFT, thread = y
        int y = tid;
        float aR[16], aI[16];
        #pragma unroll
        for (int k = 0; k < 16; k++) { aR[k] = 0.f; aI[k] = 0.f; }
        for (int kyi = 0; kyi < 32; kyi++) {
            int ky = (kyi < 16) ? kyi : kyi + 224;
            int j = (ky * y) & 255;
            float cv = csm[j], sv = ssm[j];
            const float* ob = &oft_s[kyi*32];
            #pragma unroll
            for (int kx = 0; kx < 16; kx++) {
                float orr = ob[2*kx], oii = ob[2*kx+1];
                aR[kx] += orr*cv - oii*sv;            // (or+ioi)(c + i s)
                aI[kx] += orr*sv + oii*cv;
            }
        }
        #pragma unroll
        for (int kx = 0; kx < 16; kx++) {
            tmp[y*33 + 2*kx]   = aR[kx];
            tmp[y*33 + 2*kx+1] = aI[kx];
        }
    }
    __syncthreads();
    {   // phase 3: x synthesis, thread = x (column); table cached in regs
        int x = tid;
        float f[32];
        #pragma unroll
        for (int n = 0; n < 32; n++) f[n] = g_tabFT[n*256 + x];
        float* gdst = g_G + (size_t)img * 65536;
        for (int y = 0; y < 256; y++) {
            const float* tr = &tmp[y*33];
            float a0 = 0.f, a1 = 0.f, a2 = 0.f, a3 = 0.f;
            #pragma unroll
            for (int n = 0; n < 32; n += 4) {
                a0 += tr[n+0] * f[n+0];
                a1 += tr[n+1] * f[n+1];
                a2 += tr[n+2] * f[n+2];
                a3 += tr[n+3] * f[n+3];
            }
            gdst[y*256 + x] = (a0 + a1) + (a2 + a3);
        }
    }
}

// ---------------- Kernel E: 3x3 circular conv (f32x2) * G -> out ----------------
// grid (1, 128, 16), 256 thr; thread computes 2 vertical pixels x 64 co
#define CI_CHUNK 16
__global__ void __launch_bounds__(256, 1) kE(const float* __restrict__ c,
                                             const float* __restrict__ bias,
                                             float* __restrict__ out) {
    __shared__ float wsm[CI_CHUNK * 576];             // 36 KB
    int tid = threadIdx.x;
    int x  = tid;
    int y0 = blockIdx.y * 2;
    int b  = blockIdx.z;
    int xm1 = (x + 255) & 255, xp1 = (x + 1) & 255;
    int ym1 = (y0 + 255) & 255, y1 = y0 + 1, yp2 = (y0 + 2) & 255;

    unsigned long long accT[32], accB[32];
    #pragma unroll
    for (int p = 0; p < 32; p++) { accT[p] = 0ULL; accB[p] = 0ULL; }

    const float* cb = c + (size_t)b * 64 * 65536;

    for (int cc = 0; cc < 64 / CI_CHUNK; cc++) {
        __syncthreads();
        {   // stage this chunk's weights
            const float4* wsrc = (const float4*)(g_wT + cc * (CI_CHUNK*576));
            float4* wdst = (float4*)wsm;
            for (int i = tid; i < CI_CHUNK*576/4; i += 256) wdst[i] = wsrc[i];
        }
        __syncthreads();

        for (int ci2 = 0; ci2 < CI_CHUNK; ci2++) {
            int ci = cc * CI_CHUNK + ci2;
            const float* ccp = cb + (size_t)ci * 65536;
            const float* r0 = ccp + ym1 * 256;
            const float* r1 = ccp + y0  * 256;
            const float* r2 = ccp + y1  * 256;
            const float* r3 = ccp + yp2 * 256;
            float v0a = r0[xm1], v0b = r0[x], v0c = r0[xp1];
            float v1a = r1[xm1], v1b = r1[x], v1c = r1[xp1];
            float v2a = r2[xm1], v2b = r2[x], v2c = r2[xp1];
            float v3a = r3[xm1], v3b = r3[x], v3c = r3[xp1];
            float topv[9] = { v0a, v0b, v0c, v1a, v1b, v1c, v2a, v2b, v2c };
            float botv[9] = { v1a, v1b, v1c, v2a, v2b, v2c, v3a, v3b, v3c };
            const float* wbase = wsm + ci2 * 576;
            #pragma unroll
            for (int t = 0; t < 9; t++) {
                unsigned long long vt = pack2(topv[t]);
                unsigned long long vb = pack2(botv[t]);
                const ulonglong2* wp = (const ulonglong2*)(wbase + t * 64);
                #pragma unroll
                for (int q = 0; q < 16; q++) {
                    ulonglong2 wv = wp[q];
                    accT[2*q]   = fma2(vt, wv.x, accT[2*q]);
                    accT[2*q+1] = fma2(vt, wv.y, accT[2*q+1]);
                    accB[2*q]   = fma2(vb, wv.x, accB[2*q]);
                    accB[2*q+1] = fma2(vb, wv.y, accB[2*q+1]);
                }
            }
        }
    }

    // epilogue: add bias, multiply by global branch, store
    size_t obase = (size_t)b * 64 * 65536;
    #pragma unroll
    for (int p = 0; p < 32; p++) {
        float t0, t1, b0, b1;
        asm("mov.b64 {%0,%1}, %2;" : "=f"(t0), "=f"(t1) : "l"(accT[p]));
        asm("mov.b64 {%0,%1}, %2;" : "=f"(b0), "=f"(b1) : "l"(accB[p]));
        int co0 = 2*p, co1 = 2*p + 1;
        float bi0 = bias[co0], bi1 = bias[co1];
        size_t i00 = obase + (size_t)co0 * 65536 + (size_t)y0 * 256 + x;
        size_t i01 = obase + (size_t)co1 * 65536 + (size_t)y0 * 256 + x;
        out[i00]       = (t0 + bi0) * g_G[i00];
        out[i00 + 256] = (b0 + bi0) * g_G[i00 + 256];
        out[i01]       = (t1 + bi1) * g_G[i01];
        out[i01 + 256] = (b1 + bi1) * g_G[i01 + 256];
    }
}

// ---------------- launch ----------------
extern "C" void kernel_launch(void* const* d_in, const int* in_sizes, int n_in,
                              void* d_out, int out_size) {
    const float* c      = (const float*)d_in[0];
    const float* w1r    = (const float*)d_in[1];
    const float* w1i    = (const float*)d_in[2];
    const float* w2r    = (const float*)d_in[3];
    const float* w2i    = (const float*)d_in[4];
    const float* conv_w = (const float*)d_in[5];
    const float* conv_b = (const float*)d_in[6];
    float* out = (float*)d_out;

    k_init<<<64, 256>>>(conv_w);
    kA<<<2048, 256>>>(c);
    kB<<<1024, 512>>>();
    kC<<<512, 128>>>(w1r, w1i, w2r, w2i);
    kD<<<1024, 256>>>();
    dim3 gE(1, 128, 16);
    kE<<<gE, 256>>>(c, conv_b, out);
}

// round 2
// speedup vs baseline: 1.2854x; 1.2854x over previous
#include <cuda_runtime.h>
#include <math.h>

#define BB   16
#define CH   64
#define HH   256
#define WW   256
#define MD   16
#define NIMG (BB*CH)   // 1024

// ---------------- scratch (static __device__ allocations only) ----------------
__device__ __align__(16) float g_X1 [NIMG*HH*32];     // 33.5 MB  [img][y][2kx+ri]
__device__ __align__(16) float g_CFT[NIMG*512*2];     // 4 MB     [img][m][ri], m=kyi*16+kx
__device__ __align__(16) float g_OFT[NIMG*512*2];     // 4 MB
__device__ __align__(16) float g_G  [NIMG*HH*WW];     // 268 MB   global-branch output
__device__ __align__(16) float g_tabA [256*32];       // forward x-DFT twiddles [x][n]
__device__ __align__(16) float g_tabFT[32*256];       // inverse x-synth (scaled) [n][x]
__device__ __align__(16) float g_cosT[256];
__device__ __align__(16) float g_sinT[256];
__device__ __align__(16) float g_wT [CH*9*CH];        // conv weights [ci][tap][co]

// ---------------- f32x2 helpers ----------------
__device__ __forceinline__ unsigned long long pack2(float v) {
    unsigned long long d;
    asm("mov.b64 %0, {%1, %2};" : "=l"(d) : "f"(v), "f"(v));
    return d;
}
__device__ __forceinline__ unsigned long long packf2(float lo, float hi) {
    unsigned long long d;
    asm("mov.b64 %0, {%1, %2};" : "=l"(d) : "f"(lo), "f"(hi));
    return d;
}
__device__ __forceinline__ unsigned long long fma2(unsigned long long a,
                                                   unsigned long long b,
                                                   unsigned long long c) {
    unsigned long long d;
    asm("fma.rn.f32x2 %0, %1, %2, %3;" : "=l"(d) : "l"(a), "l"(b), "l"(c));
    return d;
}
__device__ __forceinline__ void unpack2(unsigned long long v, float& lo, float& hi) {
    asm("mov.b64 {%0,%1}, %2;" : "=f"(lo), "=f"(hi) : "l"(v));
}

// ---------------- init: twiddle tables + conv weight reorder ----------------
__global__ void k_init(const float* __restrict__ conv_w) {
    const float TWO_PI = 6.28318530717958647692f;
    int tid = blockIdx.x * blockDim.x + threadIdx.x;
    int stride = gridDim.x * blockDim.x;

    if (tid < 256) {
        float ang = TWO_PI * (float)tid / 256.0f;
        g_cosT[tid] = cosf(ang);
        g_sinT[tid] = sinf(ang);
    }
    // forward table: [x][n], n=2kx -> cos, n=2kx+1 -> -sin   (e^{-i t})
    for (int idx = tid; idx < 256*32; idx += stride) {
        int x = idx >> 5, n = idx & 31, kx = n >> 1;
        float ang = TWO_PI * (float)((kx * x) & 255) / 256.0f;
        g_tabA[idx] = (n & 1) ? -sinf(ang) : cosf(ang);
    }
    // inverse synth table: [n][x], scaled (DC x1, others x2, /65536)
    for (int idx = tid; idx < 32*256; idx += stride) {
        int n = idx >> 8, x = idx & 255, kx = n >> 1;
        float sc = (kx == 0 ? 1.0f : 2.0f) / 65536.0f;
        float ang = TWO_PI * (float)((kx * x) & 255) / 256.0f;
        g_tabFT[idx] = (n & 1) ? -sc * sinf(ang) : sc * cosf(ang);
    }
    // conv weights OIHW -> [ci][tap][co]
    for (int idx = tid; idx < CH*9*CH; idx += stride) {
        int co = idx & 63;
        int rest = idx >> 6;
        int t  = rest % 9;
        int ci = rest / 9;
        g_wT[idx] = conv_w[(co*CH + ci)*9 + t];
    }
}

// ---------------- Kernel A: partial x-DFT (kx 0..15), real -> complex ----------------
__global__ void __launch_bounds__(256) kA(const float* __restrict__ c) {
    __shared__ float tab[8192];
    __shared__ float rows[8][256];
    int tid = threadIdx.x;
    for (int i = tid; i < 8192; i += 256) tab[i] = g_tabA[i];
    __syncthreads();
    int w = tid >> 5, lane = tid & 31;
    int rowBase = blockIdx.x * 128;
    for (int it = 0; it < 16; it++) {
        int row = rowBase + it*8 + w;                 // global row = img*256 + y
        const float* src = c + (size_t)row * 256;
        #pragma unroll
        for (int k = 0; k < 8; k++) rows[w][lane + k*32] = src[lane + k*32];
        __syncwarp();
        float a0 = 0.f, a1 = 0.f, a2 = 0.f, a3 = 0.f;
        #pragma unroll 4
        for (int x = 0; x < 256; x += 4) {
            a0 += rows[w][x+0] * tab[(x+0)*32 + lane];
            a1 += rows[w][x+1] * tab[(x+1)*32 + lane];
            a2 += rows[w][x+2] * tab[(x+2)*32 + lane];
            a3 += rows[w][x+3] * tab[(x+3)*32 + lane];
        }
        g_X1[(size_t)row*32 + lane] = (a0 + a1) + (a2 + a3);
        __syncwarp();
    }
}

// ---------------- Kernel B: y-DFT to 32 ky modes ----------------
__global__ void __launch_bounds__(512) kB() {
    __shared__ float xs[8192];
    __shared__ float csm[256], ssm[256];
    int tid = threadIdx.x;
    int img = blockIdx.x;
    const float* src = g_X1 + (size_t)img * 8192;
    for (int i = tid; i < 8192; i += 512) xs[i] = src[i];
    if (tid < 256) { csm[tid] = g_cosT[tid]; ssm[tid] = g_sinT[tid]; }
    __syncthreads();
    int kyi = tid >> 4, kx = tid & 15;
    int ky = (kyi < 16) ? kyi : kyi + 224;            // 240..255
    float ar = 0.f, ai = 0.f;
    for (int y = 0; y < 256; y++) {
        int j = (ky * y) & 255;
        float cv = csm[j], sv = ssm[j];
        float2 v = *(const float2*)&xs[y*32 + 2*kx];
        ar += v.x * cv + v.y * sv;                    // (xr+ixi)(c - i s)
        ai += v.y * cv - v.x * sv;
    }
    *(float2*)&g_CFT[((size_t)img*512 + tid)*2] = make_float2(ar, ai);
}

// ---------------- Kernel C: per-mode 64x64 complex channel mix ----------------
__global__ void __launch_bounds__(128) kC(const float* __restrict__ w1r, const float* __restrict__ w1i,
                                          const float* __restrict__ w2r, const float* __restrict__ w2i) {
    __shared__ float wr_s[4096], wi_s[4096], cf_s[2048];
    int tid = threadIdx.x;
    int m = blockIdx.x;
    int kyi = m >> 4, kx = m & 15;
    const float* br; const float* bi; int woff;
    if (kyi < 16) { br = w1r; bi = w1i; woff = kyi*16 + kx; }
    else          { br = w2r; bi = w2i; woff = (kyi-16)*16 + kx; }
    for (int idx = tid; idx < 4096; idx += 128) {     // idx = i*64+o
        wr_s[idx] = br[idx*256 + woff];
        wi_s[idx] = bi[idx*256 + woff];
    }
    for (int idx = tid; idx < 1024; idx += 128) {     // idx = b*64+i
        float2 v = *(const float2*)&g_CFT[((size_t)idx*512 + m)*2];
        cf_s[2*idx] = v.x; cf_s[2*idx+1] = v.y;
    }
    __syncthreads();
    int o = tid & 63, h = tid >> 6;                   // h in {0,1}, 8 batches each
    float aR[8], aI[8];
    #pragma unroll
    for (int q = 0; q < 8; q++) { aR[q] = 0.f; aI[q] = 0.f; }
    for (int i = 0; i < 64; i++) {
        float wr = wr_s[i*64 + o], wi = wi_s[i*64 + o];
        #pragma unroll
        for (int q = 0; q < 8; q++) {
            int b = h*8 + q;
            float cr = cf_s[(b*64 + i)*2], ci2 = cf_s[(b*64 + i)*2 + 1];
            aR[q] += cr*wr - ci2*wi;
            aI[q] += cr*wi + ci2*wr;
        }
    }
    #pragma unroll
    for (int q = 0; q < 8; q++) {
        int b = h*8 + q;
        *(float2*)&g_OFT[(((size_t)b*64 + o)*512 + m)*2] = make_float2(aR[q], aI[q]);
    }
}

// ---------------- Kernel D: inverse transform -> G ----------------
// 1024 blocks (one per output image), 256 thr
__global__ void __launch_bounds__(256) kD() {
    __shared__ float tmp[256*34];                     // padded stride 34 (8B-aligned pairs)
    __shared__ float oft_s[1024];
    __shared__ float csm[256], ssm[256];
    int tid = threadIdx.x;
    int img = blockIdx.x;
    const float* src = g_OFT + (size_t)img * 1024;
    for (int i = tid; i < 1024; i += 256) oft_s[i] = src[i];
    if (tid < 256) { csm[tid] = g_cosT[tid]; ssm[tid] = g_sinT[tid]; }
    __syncthreads();
    {   // phase 2: y-iDFT, thread = y
        int y = tid;
        float aR[16], aI[16];
        #pragma unroll
        for (int k = 0; k < 16; k++) { aR[k] = 0.f; aI[k] = 0.f; }
        for (int kyi = 0; kyi < 32; kyi++) {
            int ky = (kyi < 16) ? kyi : kyi + 224;
            int j = (ky * y) & 255;
            float cv = csm[j], sv = ssm[j];
            const float* ob = &oft_s[kyi*32];
            #pragma unroll
            for (int kx = 0; kx < 16; kx++) {
                float orr = ob[2*kx], oii = ob[2*kx+1];
                aR[kx] += orr*cv - oii*sv;            // (or+ioi)(c + i s)
                aI[kx] += orr*sv + oii*cv;
            }
        }
        #pragma unroll
        for (int kx = 0; kx < 16; kx++) {
            tmp[y*34 + 2*kx]   = aR[kx];
            tmp[y*34 + 2*kx+1] = aI[kx];
        }
    }
    __syncthreads();
    {   // phase 3: x synthesis with f32x2, thread = x (column)
        int x = tid;
        unsigned long long f2[16];
        #pragma unroll
        for (int n2 = 0; n2 < 16; n2++)
            f2[n2] = packf2(g_tabFT[(2*n2)*256 + x], g_tabFT[(2*n2+1)*256 + x]);
        float* gdst = g_G + (size_t)img * 65536;
        for (int y = 0; y < 256; y++) {
            const unsigned long long* tr = (const unsigned long long*)&tmp[y*34];
            unsigned long long a0 = 0ULL, a1 = 0ULL, a2 = 0ULL, a3 = 0ULL;
            #pragma unroll
            for (int n2 = 0; n2 < 16; n2 += 4) {
                a0 = fma2(tr[n2+0], f2[n2+0], a0);
                a1 = fma2(tr[n2+1], f2[n2+1], a1);
                a2 = fma2(tr[n2+2], f2[n2+2], a2);
                a3 = fma2(tr[n2+3], f2[n2+3], a3);
            }
            float s0,s1,s2,s3,s4,s5,s6,s7;
            unpack2(a0, s0, s1); unpack2(a1, s2, s3);
            unpack2(a2, s4, s5); unpack2(a3, s6, s7);
            gdst[y*256 + x] = ((s0+s1)+(s2+s3)) + ((s4+s5)+(s6+s7));
        }
    }
}

// ---------------- Kernel E: 3x3 circular conv (f32x2) * G -> out ----------------
// grid (1, 128, 16), 512 thr; thread computes 2 vertical pixels x 32 co (half split)
#define CI_CHUNK 16

__device__ __forceinline__ void loadv12(const float* ccp, int xm1, int x, int xp1,
                                        int ym1, int y0, int y1, int yp2, float v[12]) {
    const float* r0 = ccp + ym1 * 256;
    const float* r1 = ccp + y0  * 256;
    const float* r2 = ccp + y1  * 256;
    const float* r3 = ccp + yp2 * 256;
    v[0] = r0[xm1]; v[1]  = r0[x]; v[2]  = r0[xp1];
    v[3] = r1[xm1]; v[4]  = r1[x]; v[5]  = r1[xp1];
    v[6] = r2[xm1]; v[7]  = r2[x]; v[8]  = r2[xp1];
    v[9] = r3[xm1]; v[10] = r3[x]; v[11] = r3[xp1];
}

__device__ __forceinline__ void compute_ci(const float v[12], const float* wbase,
                                           unsigned long long accT[16],
                                           unsigned long long accB[16]) {
    #pragma unroll
    for (int t = 0; t < 9; t++) {
        unsigned long long vt = pack2(v[t]);
        unsigned long long vb = pack2(v[t + 3]);
        const ulonglong2* wp = (const ulonglong2*)(wbase + t * 64);
        #pragma unroll
        for (int q = 0; q < 8; q++) {
            ulonglong2 wv = wp[q];
            accT[2*q]   = fma2(vt, wv.x, accT[2*q]);
            accT[2*q+1] = fma2(vt, wv.y, accT[2*q+1]);
            accB[2*q]   = fma2(vb, wv.x, accB[2*q]);
            accB[2*q+1] = fma2(vb, wv.y, accB[2*q+1]);
        }
    }
}

__global__ void __launch_bounds__(512, 1) kE(const float* __restrict__ c,
                                             const float* __restrict__ bias,
                                             float* __restrict__ out) {
    __shared__ float wsm[CI_CHUNK * 576];             // 36 KB
    int tid = threadIdx.x;
    int x    = tid & 255;
    int half = tid >> 8;                              // 0 or 1 -> co 0..31 / 32..63
    int coBase = half * 32;
    int y0 = blockIdx.y * 2;
    int b  = blockIdx.z;
    int xm1 = (x + 255) & 255, xp1 = (x + 1) & 255;
    int ym1 = (y0 + 255) & 255, y1 = y0 + 1, yp2 = (y0 + 2) & 255;

    unsigned long long accT[16], accB[16];
    #pragma unroll
    for (int p = 0; p < 16; p++) { accT[p] = 0ULL; accB[p] = 0ULL; }

    const float* cb = c + (size_t)b * 64 * 65536;

    float vA[12], vB[12];
    loadv12(cb, xm1, x, xp1, ym1, y0, y1, yp2, vA);   // prefetch ci = 0

    for (int cc = 0; cc < 64 / CI_CHUNK; cc++) {
        __syncthreads();
        {   // stage this chunk's weights
            const float4* wsrc = (const float4*)(g_wT + cc * (CI_CHUNK*576));
            float4* wdst = (float4*)wsm;
            for (int i = tid; i < CI_CHUNK*576/4; i += 512) wdst[i] = wsrc[i];
        }
        __syncthreads();

        #pragma unroll 2
        for (int ci2 = 0; ci2 < CI_CHUNK; ci2++) {
            int ci = cc * CI_CHUNK + ci2;
            if (ci2 & 1) {
                if (ci < 63) loadv12(cb + (size_t)(ci+1)*65536, xm1, x, xp1, ym1, y0, y1, yp2, vA);
                compute_ci(vB, wsm + ci2*576 + coBase, accT, accB);
            } else {
                if (ci < 63) loadv12(cb + (size_t)(ci+1)*65536, xm1, x, xp1, ym1, y0, y1, yp2, vB);
                compute_ci(vA, wsm + ci2*576 + coBase, accT, accB);
            }
        }
    }

    // epilogue: add bias, multiply by global branch, store
    size_t obase = (size_t)b * 64 * 65536;
    #pragma unroll
    for (int p = 0; p < 16; p++) {
        float t0, t1, b0, b1;
        unpack2(accT[p], t0, t1);
        unpack2(accB[p], b0, b1);
        int co0 = coBase + 2*p, co1 = co0 + 1;
        float bi0 = bias[co0], bi1 = bias[co1];
        size_t i00 = obase + (size_t)co0 * 65536 + (size_t)y0 * 256 + x;
        size_t i01 = obase + (size_t)co1 * 65536 + (size_t)y0 * 256 + x;
        out[i00]       = (t0 + bi0) * g_G[i00];
        out[i00 + 256] = (b0 + bi0) * g_G[i00 + 256];
        out[i01]       = (t1 + bi1) * g_G[i01];
        out[i01 + 256] = (b1 + bi1) * g_G[i01 + 256];
    }
}

// ---------------- launch ----------------
extern "C" void kernel_launch(void* const* d_in, const int* in_sizes, int n_in,
                              void* d_out, int out_size) {
    const float* c      = (const float*)d_in[0];
    const float* w1r    = (const float*)d_in[1];
    const float* w1i    = (const float*)d_in[2];
    const float* w2r    = (const float*)d_in[3];
    const float* w2i    = (const float*)d_in[4];
    const float* conv_w = (const float*)d_in[5];
    const float* conv_b = (const float*)d_in[6];
    float* out = (float*)d_out;

    k_init<<<64, 256>>>(conv_w);
    kA<<<2048, 256>>>(c);
    kB<<<1024, 512>>>();
    kC<<<512, 128>>>(w1r, w1i, w2r, w2i);
    kD<<<1024, 256>>>();
    dim3 gE(1, 128, 16);
    kE<<<gE, 512>>>(c, conv_b, out);
}

// round 3
// speedup vs baseline: 1.4584x; 1.1346x over previous
#include <cuda_runtime.h>
#include <math.h>

#define BB   16
#define CH   64
#define HH   256
#define WW   256
#define MD   16
#define NIMG (BB*CH)   // 1024

// ---------------- scratch (static __device__ allocations only) ----------------
__device__ __align__(16) float g_X1 [NIMG*HH*32];     // 33.5 MB  [img][y][2kx+ri]
__device__ __align__(16) float g_CFT[NIMG*512*2];     // 4 MB     [img][m][ri], m=kyi*16+kx
__device__ __align__(16) float g_OFT[NIMG*512*2];     // 4 MB
__device__ __align__(16) float g_G  [NIMG*HH*WW];     // 268 MB   global-branch output
__device__ __align__(16) float g_tabA [256*32];       // forward x-DFT twiddles [x][n]
__device__ __align__(16) float g_tabFT[32*256];       // inverse x-synth (scaled) [n][x]
__device__ __align__(16) float g_cosT[256];
__device__ __align__(16) float g_sinT[256];
__device__ __align__(16) float g_wT [CH*9*CH];        // conv weights [ci][tap][co]

// ---------------- f32x2 helpers ----------------
__device__ __forceinline__ unsigned long long pack2(float v) {
    unsigned long long d;
    asm("mov.b64 %0, {%1, %2};" : "=l"(d) : "f"(v), "f"(v));
    return d;
}
__device__ __forceinline__ unsigned long long packf2(float lo, float hi) {
    unsigned long long d;
    asm("mov.b64 %0, {%1, %2};" : "=l"(d) : "f"(lo), "f"(hi));
    return d;
}
__device__ __forceinline__ unsigned long long fma2(unsigned long long a,
                                                   unsigned long long b,
                                                   unsigned long long c) {
    unsigned long long d;
    asm("fma.rn.f32x2 %0, %1, %2, %3;" : "=l"(d) : "l"(a), "l"(b), "l"(c));
    return d;
}
__device__ __forceinline__ void unpack2(unsigned long long v, float& lo, float& hi) {
    asm("mov.b64 {%0,%1}, %2;" : "=f"(lo), "=f"(hi) : "l"(v));
}

// ---------------- init: twiddle tables + conv weight reorder ----------------
__global__ void k_init(const float* __restrict__ conv_w) {
    const float TWO_PI = 6.28318530717958647692f;
    int tid = blockIdx.x * blockDim.x + threadIdx.x;
    int stride = gridDim.x * blockDim.x;

    if (tid < 256) {
        float ang = TWO_PI * (float)tid / 256.0f;
        g_cosT[tid] = cosf(ang);
        g_sinT[tid] = sinf(ang);
    }
    // forward table: [x][n], n=2kx -> cos, n=2kx+1 -> -sin   (e^{-i t})
    for (int idx = tid; idx < 256*32; idx += stride) {
        int x = idx >> 5, n = idx & 31, kx = n >> 1;
        float ang = TWO_PI * (float)((kx * x) & 255) / 256.0f;
        g_tabA[idx] = (n & 1) ? -sinf(ang) : cosf(ang);
    }
    // inverse synth table: [n][x], scaled (DC x1, others x2, /65536)
    for (int idx = tid; idx < 32*256; idx += stride) {
        int n = idx >> 8, x = idx & 255, kx = n >> 1;
        float sc = (kx == 0 ? 1.0f : 2.0f) / 65536.0f;
        float ang = TWO_PI * (float)((kx * x) & 255) / 256.0f;
        g_tabFT[idx] = (n & 1) ? -sc * sinf(ang) : sc * cosf(ang);
    }
    // conv weights OIHW -> [ci][tap][co]
    for (int idx = tid; idx < CH*9*CH; idx += stride) {
        int co = idx & 63;
        int rest = idx >> 6;
        int t  = rest % 9;
        int ci = rest / 9;
        g_wT[idx] = conv_w[(co*CH + ci)*9 + t];
    }
}

// ---------------- Kernel A: partial x-DFT (kx 0..15), real -> complex ----------------
__global__ void __launch_bounds__(256) kA(const float* __restrict__ c) {
    __shared__ float tab[8192];
    __shared__ float rows[8][256];
    int tid = threadIdx.x;
    for (int i = tid; i < 8192; i += 256) tab[i] = g_tabA[i];
    __syncthreads();
    int w = tid >> 5, lane = tid & 31;
    int rowBase = blockIdx.x * 128;
    for (int it = 0; it < 16; it++) {
        int row = rowBase + it*8 + w;                 // global row = img*256 + y
        const float* src = c + (size_t)row * 256;
        #pragma unroll
        for (int k = 0; k < 8; k++) rows[w][lane + k*32] = src[lane + k*32];
        __syncwarp();
        float a0 = 0.f, a1 = 0.f, a2 = 0.f, a3 = 0.f;
        #pragma unroll 4
        for (int x = 0; x < 256; x += 4) {
            a0 += rows[w][x+0] * tab[(x+0)*32 + lane];
            a1 += rows[w][x+1] * tab[(x+1)*32 + lane];
            a2 += rows[w][x+2] * tab[(x+2)*32 + lane];
            a3 += rows[w][x+3] * tab[(x+3)*32 + lane];
        }
        g_X1[(size_t)row*32 + lane] = (a0 + a1) + (a2 + a3);
        __syncwarp();
    }
}

// ---------------- Kernel B: y-DFT to 32 ky modes ----------------
__global__ void __launch_bounds__(512) kB() {
    __shared__ float xs[8192];
    __shared__ float csm[256], ssm[256];
    int tid = threadIdx.x;
    int img = blockIdx.x;
    const float* src = g_X1 + (size_t)img * 8192;
    for (int i = tid; i < 8192; i += 512) xs[i] = src[i];
    if (tid < 256) { csm[tid] = g_cosT[tid]; ssm[tid] = g_sinT[tid]; }
    __syncthreads();
    int kyi = tid >> 4, kx = tid & 15;
    int ky = (kyi < 16) ? kyi : kyi + 224;            // 240..255
    float ar = 0.f, ai = 0.f;
    for (int y = 0; y < 256; y++) {
        int j = (ky * y) & 255;
        float cv = csm[j], sv = ssm[j];
        float2 v = *(const float2*)&xs[y*32 + 2*kx];
        ar += v.x * cv + v.y * sv;                    // (xr+ixi)(c - i s)
        ai += v.y * cv - v.x * sv;
    }
    *(float2*)&g_CFT[((size_t)img*512 + tid)*2] = make_float2(ar, ai);
}

// ---------------- Kernel C: per-mode 64x64 complex channel mix ----------------
__global__ void __launch_bounds__(128) kC(const float* __restrict__ w1r, const float* __restrict__ w1i,
                                          const float* __restrict__ w2r, const float* __restrict__ w2i) {
    __shared__ float wr_s[4096], wi_s[4096], cf_s[2048];
    int tid = threadIdx.x;
    int m = blockIdx.x;
    int kyi = m >> 4, kx = m & 15;
    const float* br; const float* bi; int woff;
    if (kyi < 16) { br = w1r; bi = w1i; woff = kyi*16 + kx; }
    else          { br = w2r; bi = w2i; woff = (kyi-16)*16 + kx; }
    for (int idx = tid; idx < 4096; idx += 128) {     // idx = i*64+o
        wr_s[idx] = br[idx*256 + woff];
        wi_s[idx] = bi[idx*256 + woff];
    }
    for (int idx = tid; idx < 1024; idx += 128) {     // idx = b*64+i
        float2 v = *(const float2*)&g_CFT[((size_t)idx*512 + m)*2];
        cf_s[2*idx] = v.x; cf_s[2*idx+1] = v.y;
    }
    __syncthreads();
    int o = tid & 63, h = tid >> 6;                   // h in {0,1}, 8 batches each
    float aR[8], aI[8];
    #pragma unroll
    for (int q = 0; q < 8; q++) { aR[q] = 0.f; aI[q] = 0.f; }
    for (int i = 0; i < 64; i++) {
        float wr = wr_s[i*64 + o], wi = wi_s[i*64 + o];
        #pragma unroll
        for (int q = 0; q < 8; q++) {
            int b = h*8 + q;
            float cr = cf_s[(b*64 + i)*2], ci2 = cf_s[(b*64 + i)*2 + 1];
            aR[q] += cr*wr - ci2*wi;
            aI[q] += cr*wi + ci2*wr;
        }
    }
    #pragma unroll
    for (int q = 0; q < 8; q++) {
        int b = h*8 + q;
        *(float2*)&g_OFT[(((size_t)b*64 + o)*512 + m)*2] = make_float2(aR[q], aI[q]);
    }
}

// ---------------- Kernel D: inverse transform -> G ----------------
// 1024 blocks (one per output image), 256 thr
__global__ void __launch_bounds__(256) kD() {
    __shared__ float tmp[256*34];                     // padded stride 34 (8B-aligned pairs)
    __shared__ float oft_s[1024];
    __shared__ float csm[256], ssm[256];
    int tid = threadIdx.x;
    int img = blockIdx.x;
    const float* src = g_OFT + (size_t)img * 1024;
    for (int i = tid; i < 1024; i += 256) oft_s[i] = src[i];
    if (tid < 256) { csm[tid] = g_cosT[tid]; ssm[tid] = g_sinT[tid]; }
    __syncthreads();
    {   // phase 2: y-iDFT, thread = y
        int y = tid;
        float aR[16], aI[16];
        #pragma unroll
        for (int k = 0; k < 16; k++) { aR[k] = 0.f; aI[k] = 0.f; }
        for (int kyi = 0; kyi < 32; kyi++) {
            int ky = (kyi < 16) ? kyi : kyi + 224;
            int j = (ky * y) & 255;
            float cv = csm[j], sv = ssm[j];
            const float* ob = &oft_s[kyi*32];
            #pragma unroll
            for (int kx = 0; kx < 16; kx++) {
                float orr = ob[2*kx], oii = ob[2*kx+1];
                aR[kx] += orr*cv - oii*sv;            // (or+ioi)(c + i s)
                aI[kx] += orr*sv + oii*cv;
            }
        }
        #pragma unroll
        for (int kx = 0; kx < 16; kx++) {
            tmp[y*34 + 2*kx]   = aR[kx];
            tmp[y*34 + 2*kx+1] = aI[kx];
        }
    }
    __syncthreads();
    {   // phase 3: x synthesis with f32x2, thread = x (column)
        int x = tid;
        unsigned long long f2[16];
        #pragma unroll
        for (int n2 = 0; n2 < 16; n2++)
            f2[n2] = packf2(g_tabFT[(2*n2)*256 + x], g_tabFT[(2*n2+1)*256 + x]);
        float* gdst = g_G + (size_t)img * 65536;
        for (int y = 0; y < 256; y++) {
            const unsigned long long* tr = (const unsigned long long*)&tmp[y*34];
            unsigned long long a0 = 0ULL, a1 = 0ULL, a2 = 0ULL, a3 = 0ULL;
            #pragma unroll
            for (int n2 = 0; n2 < 16; n2 += 4) {
                a0 = fma2(tr[n2+0], f2[n2+0], a0);
                a1 = fma2(tr[n2+1], f2[n2+1], a1);
                a2 = fma2(tr[n2+2], f2[n2+2], a2);
                a3 = fma2(tr[n2+3], f2[n2+3], a3);
            }
            float s0,s1,s2,s3,s4,s5,s6,s7;
            unpack2(a0, s0, s1); unpack2(a1, s2, s3);
            unpack2(a2, s4, s5); unpack2(a3, s6, s7);
            gdst[y*256 + x] = ((s0+s1)+(s2+s3)) + ((s4+s5)+(s6+s7));
        }
    }
}

// ---------------- Kernel E: 3x3 circular conv (f32x2) * G -> out ----------------
// grid (8, 64, 16), 256 thr = 32 x-lanes x 8 co-groups.
// Thread computes 4 vertical pixels x 8 co.
#define CI_CHUNK 16

__device__ __forceinline__ void loadv18(const float* __restrict__ ccp, const int rofs[6],
                                        int xm1, int x, int xp1, float v[18]) {
    #pragma unroll
    for (int r = 0; r < 6; r++) {
        const float* rp = ccp + rofs[r];
        v[r*3+0] = rp[xm1]; v[r*3+1] = rp[x]; v[r*3+2] = rp[xp1];
    }
}

// acc[p*4+q]: pixel p (0..3), co-pair q (0..3)
__device__ __forceinline__ void compute_ci(const float v[18], const float* wbase,
                                           unsigned long long acc[16]) {
    unsigned long long pv[18];
    #pragma unroll
    for (int i = 0; i < 18; i++) pv[i] = pack2(v[i]);
    #pragma unroll
    for (int dy = 0; dy < 3; dy++) {
        #pragma unroll
        for (int d = 0; d < 3; d++) {
            const ulonglong2* wp = (const ulonglong2*)(wbase + (dy*3 + d)*64);
            ulonglong2 w0 = wp[0];
            ulonglong2 w1 = wp[1];
            #pragma unroll
            for (int p = 0; p < 4; p++) {
                unsigned long long vv = pv[(p + dy)*3 + d];
                acc[p*4+0] = fma2(vv, w0.x, acc[p*4+0]);
                acc[p*4+1] = fma2(vv, w0.y, acc[p*4+1]);
                acc[p*4+2] = fma2(vv, w1.x, acc[p*4+2]);
                acc[p*4+3] = fma2(vv, w1.y, acc[p*4+3]);
            }
        }
    }
}

__global__ void __launch_bounds__(256, 2) kE(const float* __restrict__ c,
                                             const float* __restrict__ bias,
                                             float* __restrict__ out) {
    __shared__ float wsm[CI_CHUNK * 576];             // 36 KB
    int tid = threadIdx.x;
    int x      = blockIdx.x * 32 + (tid & 31);
    int cog    = tid >> 5;                            // 0..7
    int coBase = cog * 8;
    int y0 = blockIdx.y * 4;
    int b  = blockIdx.z;
    int xm1 = (x + 255) & 255, xp1 = (x + 1) & 255;
    int rofs[6];
    rofs[0] = ((y0 + 255) & 255) * 256;
    rofs[1] = y0 * 256;
    rofs[2] = (y0 + 1) * 256;
    rofs[3] = (y0 + 2) * 256;
    rofs[4] = (y0 + 3) * 256;
    rofs[5] = ((y0 + 4) & 255) * 256;

    unsigned long long acc[16];
    #pragma unroll
    for (int p = 0; p < 16; p++) acc[p] = 0ULL;

    const float* cb = c + (size_t)b * 64 * 65536;

    float vA[18], vB[18];
    loadv18(cb, rofs, xm1, x, xp1, vA);               // prefetch ci = 0

    for (int cc = 0; cc < 64 / CI_CHUNK; cc++) {
        __syncthreads();
        {   // stage this chunk's weights [ci2][tap][co]
            const float4* wsrc = (const float4*)(g_wT + cc * (CI_CHUNK*576));
            float4* wdst = (float4*)wsm;
            #pragma unroll
            for (int i = 0; i < CI_CHUNK*576/4/256; i++)
                wdst[tid + i*256] = wsrc[tid + i*256];
        }
        __syncthreads();

        #pragma unroll 2
        for (int ci2 = 0; ci2 < CI_CHUNK; ci2++) {
            int ci = cc * CI_CHUNK + ci2;
            if (ci2 & 1) {
                if (ci < 63) loadv18(cb + (size_t)(ci+1)*65536, rofs, xm1, x, xp1, vA);
                compute_ci(vB, wsm + ci2*576 + coBase, acc);
            } else {
                if (ci < 63) loadv18(cb + (size_t)(ci+1)*65536, rofs, xm1, x, xp1, vB);
                compute_ci(vA, wsm + ci2*576 + coBase, acc);
            }
        }
    }

    // epilogue: add bias, multiply by global branch, store
    size_t obase = (size_t)b * 64 * 65536;
    #pragma unroll
    for (int q = 0; q < 4; q++) {
        int co0 = coBase + 2*q, co1 = co0 + 1;
        float bi0 = bias[co0], bi1 = bias[co1];
        size_t c0 = obase + (size_t)co0 * 65536 + (size_t)y0 * 256 + x;
        size_t c1 = obase + (size_t)co1 * 65536 + (size_t)y0 * 256 + x;
        #pragma unroll
        for (int p = 0; p < 4; p++) {
            float e0, e1;
            unpack2(acc[p*4 + q], e0, e1);
            out[c0 + p*256] = (e0 + bi0) * g_G[c0 + p*256];
            out[c1 + p*256] = (e1 + bi1) * g_G[c1 + p*256];
        }
    }
}

// ---------------- launch ----------------
extern "C" void kernel_launch(void* const* d_in, const int* in_sizes, int n_in,
                              void* d_out, int out_size) {
    const float* c      = (const float*)d_in[0];
    const float* w1r    = (const float*)d_in[1];
    const float* w1i    = (const float*)d_in[2];
    const float* w2r    = (const float*)d_in[3];
    const float* w2i    = (const float*)d_in[4];
    const float* conv_w = (const float*)d_in[5];
    const float* conv_b = (const float*)d_in[6];
    float* out = (float*)d_out;

    k_init<<<64, 256>>>(conv_w);
    kA<<<2048, 256>>>(c);
    kB<<<1024, 512>>>();
    kC<<<512, 128>>>(w1r, w1i, w2r, w2i);
    kD<<<1024, 256>>>();
    dim3 gE(8, 64, 16);
    kE<<<gE, 256>>>(c, conv_b, out);
}